// round 3
// baseline (speedup 1.0000x reference)
#include <cuda_runtime.h>

// GruAeModel: B=1024, S=1024, F=36, H=20.
// Round 3: 1 elem/warp, 8 warps/block (2 warps/SMSP).
// Encoder: gi = Wih@x pipelined 2 steps ahead (independent work hides h-chain).
// Decoder: h kept in register pairs via shfl fan-out (no smem h), 1 sync/step.

#define HH 20
#define FF 36
#define RR 12
#define BB 1024
#define SS 1024
#define NWARPS 8
#define NTHREADS 256
#define FULLM 0xffffffffu

typedef unsigned long long u64;

__device__ __forceinline__ u64 ffma2(u64 a, u64 b, u64 c) {
    u64 d;
    asm("fma.rn.f32x2 %0, %1, %2, %3;" : "=l"(d) : "l"(a), "l"(b), "l"(c));
    return d;
}
__device__ __forceinline__ u64 fadd2(u64 a, u64 b) {
    u64 d;
    asm("add.rn.f32x2 %0, %1, %2;" : "=l"(d) : "l"(a), "l"(b));
    return d;
}
__device__ __forceinline__ float fold2(u64 a) {
    float lo = __uint_as_float((unsigned)a);
    float hi = __uint_as_float((unsigned)(a >> 32));
    return lo + hi;
}
__device__ __forceinline__ u64 pack2(float lo, float hi) {
    u64 d;
    asm("mov.b64 %0, {%1, %2};" : "=l"(d) : "f"(lo), "f"(hi));
    return d;
}
__device__ __forceinline__ float sigf(float x) {
    float e = __expf(-x);
    return __fdividef(1.0f, 1.0f + e);
}
__device__ __forceinline__ float tanhfast(float x) {
    float e = __expf(2.0f * x);
    return 1.0f - __fdividef(2.0f, 1.0f + e);
}

__global__ __launch_bounds__(NTHREADS, 1) void gruae_kernel(
    const float* __restrict__ x, const int* __restrict__ oneh,
    const float* __restrict__ e0t, const float* __restrict__ e1t,
    const float* __restrict__ e2t, const float* __restrict__ e3t,
    const float* __restrict__ Wih1, const float* __restrict__ Whh1,
    const float* __restrict__ bih1, const float* __restrict__ bhh1,
    const float* __restrict__ Wih2, const float* __restrict__ Whh2,
    const float* __restrict__ bih2, const float* __restrict__ bhh2,
    const float* __restrict__ Wfc, const float* __restrict__ bfc,
    float* __restrict__ out) {
    __shared__ __align__(16) float etab[1320];       // e0(40) e1@40 e2@120 e3@520
    __shared__ __align__(16) float XS[NWARPS][40];   // xin exchange (F=36 pad)
    __shared__ __align__(16) float HS[NWARPS][24];   // encoder h

    const int tid = threadIdx.x;
    const int wid = tid >> 5;
    const int lane = tid & 31;

    for (int i = tid; i < 40; i += NTHREADS) etab[i] = e0t[i];
    for (int i = tid; i < 80; i += NTHREADS) etab[40 + i] = e1t[i];
    for (int i = tid; i < 400; i += NTHREADS) etab[120 + i] = e2t[i];
    for (int i = tid; i < 800; i += NTHREADS) etab[520 + i] = e3t[i];

    const int b = blockIdx.x * NWARPS + wid;
    float* const xsh = XS[wid];
    float* const hsh = HS[wid];

    // gate mapping: lane<20 -> rows l (r), 20+l (z); lane 20+k -> rows 40+k, 50+k (n)
    const int gA = (lane < 20) ? lane : lane + 20;
    const int gB = (lane < 20) ? lane + 20 : lane + 30;
    const int nsrc = 20 + (lane % 10);
    const bool nlo = (lane < 10);

    u64 wiA[18], wiB[18], whA[10], whB[10];
    float biA = 0.f, biB = 0.f, bhA = 0.f, bhB = 0.f;
    if (lane < 30) {
        const u64* ra = (const u64*)(Wih1 + gA * FF);
        const u64* rb = (const u64*)(Wih1 + gB * FF);
#pragma unroll
        for (int j = 0; j < 18; j++) { wiA[j] = ra[j]; wiB[j] = rb[j]; }
        const u64* ha = (const u64*)(Whh1 + gA * HH);
        const u64* hb = (const u64*)(Whh1 + gB * HH);
#pragma unroll
        for (int j = 0; j < 10; j++) { whA[j] = ha[j]; whB[j] = hb[j]; }
        biA = bih1[gA]; biB = bih1[gB]; bhA = bhh1[gA]; bhB = bhh1[gB];
    }
    if (lane < HH) hsh[lane] = 0.f;
    __syncthreads();

    // input streams: lane<12 raw x col lane; lanes 12..15 onehot col lane-12
    const float* xptr = x + (size_t)b * SS * RR + lane;
    const int* optr = oneh + (size_t)b * SS * 4 + (lane - 12);
    float xq0 = 0.f, xq1 = 0.f, xq2 = 0.f;
    int oq0 = 0, oq1 = 0, oq2 = 0;
    if (lane < 12) {
        xq0 = xptr[0]; xq1 = xptr[RR]; xq2 = xptr[2 * RR]; xptr += 3 * RR;
    } else if (lane < 16) {
        oq0 = optr[0]; oq1 = optr[4]; oq2 = optr[8]; optr += 12;
    }
    const int ec = lane - 12;
    const int edim = (ec < 2) ? 4 : 8;
    const int eoff = (ec == 0) ? 12 : (ec == 1) ? 16 : (ec == 2) ? 20 : 28;
    const int etb = (ec == 0) ? 0 : (ec == 1) ? 40 : (ec == 2) ? 120 : 520;

    float* const origin = out + (size_t)b * SS * FF;
    float* const xsout = out + (size_t)(BB + b) * SS * FF;

    // build xin_u into XS, write origin_u, compute gi_u (pipelined)
    auto build_gi = [&](int u, float& giA, float& giB) {
        __syncwarp();
        if (lane < 12) {
            xsh[lane] = xq0;
        } else if (lane < 16) {
            const float* tb = etab + etb + oq0 * edim;
#pragma unroll
            for (int i = 0; i < 4; i++) xsh[eoff + i] = tb[i];
            if (edim == 8) {
#pragma unroll
                for (int i = 4; i < 8; i++) xsh[eoff + i] = tb[i];
            }
        }
        xq0 = xq1; xq1 = xq2; oq0 = oq1; oq1 = oq2;
        if (u + 3 < SS) {
            if (lane < 12)      { xq2 = xptr[0]; xptr += RR; }
            else if (lane < 16) { oq2 = optr[0]; optr += 4; }
        }
        __syncwarp();
        origin[(size_t)u * FF + lane] = xsh[lane];
        if (lane < 4) origin[(size_t)u * FF + 32 + lane] = xsh[32 + lane];
        u64 a[2] = {0, 0}, bb[2] = {0, 0};
        if (lane < 30) {
#pragma unroll
            for (int j = 0; j < 18; j++) {
                u64 xk = *(const u64*)(xsh + 2 * j);
                a[j & 1] = ffma2(wiA[j], xk, a[j & 1]);
                bb[j & 1] = ffma2(wiB[j], xk, bb[j & 1]);
            }
        }
        giA = fold2(fadd2(a[0], a[1])) + biA;
        giB = fold2(fadd2(bb[0], bb[1])) + biB;
    };

    float giA0, giB0, giA1, giB1;
    build_gi(0, giA0, giB0);
    build_gi(1, giA1, giB1);

    float hreg = 0.f;
    // ================= encoder =================
    for (int t = 0; t < SS; t++) {
        float giA2 = 0.f, giB2 = 0.f;
        if (t + 2 < SS) build_gi(t + 2, giA2, giB2);
        else __syncwarp();  // order: h store (prev iter) before h loads below
        // gh matvec for step t
        u64 hk[10];
#pragma unroll
        for (int j = 0; j < 10; j++) hk[j] = *(const u64*)(hsh + 2 * j);
        u64 a[2] = {0, 0}, bb[2] = {0, 0};
        if (lane < 30) {
#pragma unroll
            for (int j = 0; j < 10; j++) {
                a[j & 1] = ffma2(whA[j], hk[j], a[j & 1]);
                bb[j & 1] = ffma2(whB[j], hk[j], bb[j & 1]);
            }
        }
        float ghA = fold2(fadd2(a[0], a[1])) + bhA;
        float ghB = fold2(fadd2(bb[0], bb[1])) + bhB;
        // n-gate exchange
        float s_iA = __shfl_sync(FULLM, giA0, nsrc);
        float s_iB = __shfl_sync(FULLM, giB0, nsrc);
        float s_hA = __shfl_sync(FULLM, ghA, nsrc);
        float s_hB = __shfl_sync(FULLM, ghB, nsrc);
        if (lane < HH) {
            float in = nlo ? s_iA : s_iB;
            float hn = nlo ? s_hA : s_hB;
            float r = sigf(giA0 + ghA);
            float z = sigf(giB0 + ghB);
            float n = tanhfast(fmaf(r, hn, in));
            hreg = fmaf(z, hreg - n, n);
            hsh[lane] = hreg;
        }
        giA0 = giA1; giB0 = giB1; giA1 = giA2; giB1 = giB2;
    }

    // ---- handoff: h = tanh(h_last); reload decoder weights ----
    if (lane < HH) hreg = tanhfast(hreg);
    if (lane < 30) {
        const u64* ra = (const u64*)(Wih2 + gA * FF);
        const u64* rb = (const u64*)(Wih2 + gB * FF);
#pragma unroll
        for (int j = 0; j < 18; j++) { wiA[j] = ra[j]; wiB[j] = rb[j]; }
        const u64* ha = (const u64*)(Whh2 + gA * HH);
        const u64* hb = (const u64*)(Whh2 + gB * HH);
#pragma unroll
        for (int j = 0; j < 10; j++) { whA[j] = ha[j]; whB[j] = hb[j]; }
        biA = bih2[gA]; biB = bih2[gB]; bhA = bhh2[gA]; bhB = bhh2[gB];
    }
    u64 wf0[10], wf1[10];
    float bf0 = 0.f, bf1 = 0.f;
    if (lane < 18) {
        const u64* f0 = (const u64*)(Wfc + (2 * lane) * HH);
        const u64* f1 = (const u64*)(Wfc + (2 * lane + 1) * HH);
#pragma unroll
        for (int j = 0; j < 10; j++) { wf0[j] = f0[j]; wf1[j] = f1[j]; }
        bf0 = bfc[2 * lane]; bf1 = bfc[2 * lane + 1];
    }

    // h pairs in registers, all lanes (shfl fan-out)
    u64 hk[10];
    auto dist_h = [&](float hv) {
#pragma unroll
        for (int j = 0; j < 10; j++) {
            float lo = __shfl_sync(FULLM, hv, 2 * j);
            float hi = __shfl_sync(FULLM, hv, 2 * j + 1);
            hk[j] = pack2(lo, hi);
        }
    };
    // FC from hk; write smem x + global row
    auto do_fc = [&](int trow) {
        u64 a0 = 0, a1 = 0;
#pragma unroll
        for (int j = 0; j < 10; j++) {
            a0 = ffma2(wf0[j], hk[j], a0);
            a1 = ffma2(wf1[j], hk[j], a1);
        }
        if (lane < 18) {
            float v0 = tanhfast(fold2(a0) + bf0);
            float v1 = tanhfast(fold2(a1) + bf1);
            *(float2*)(xsh + 2 * lane) = make_float2(v0, v1);
            *(float2*)(xsout + (size_t)trow * FF + 2 * lane) = make_float2(v0, v1);
        }
    };

    dist_h(hreg);
    do_fc(SS - 1);
    __syncwarp();

    // ================= decoder =================
    for (int t = 1; t < SS; t++) {
        // gi from xsh, gh from hk registers
        u64 ai[2] = {0, 0}, bi[2] = {0, 0}, ah[2] = {0, 0}, bh[2] = {0, 0};
        if (lane < 30) {
#pragma unroll
            for (int j = 0; j < 18; j++) {
                u64 xk = *(const u64*)(xsh + 2 * j);
                ai[j & 1] = ffma2(wiA[j], xk, ai[j & 1]);
                bi[j & 1] = ffma2(wiB[j], xk, bi[j & 1]);
            }
#pragma unroll
            for (int j = 0; j < 10; j++) {
                ah[j & 1] = ffma2(whA[j], hk[j], ah[j & 1]);
                bh[j & 1] = ffma2(whB[j], hk[j], bh[j & 1]);
            }
        }
        float giA = fold2(fadd2(ai[0], ai[1])) + biA;
        float giB = fold2(fadd2(bi[0], bi[1])) + biB;
        float ghA = fold2(fadd2(ah[0], ah[1])) + bhA;
        float ghB = fold2(fadd2(bh[0], bh[1])) + bhB;
        float s_iA = __shfl_sync(FULLM, giA, nsrc);
        float s_iB = __shfl_sync(FULLM, giB, nsrc);
        float s_hA = __shfl_sync(FULLM, ghA, nsrc);
        float s_hB = __shfl_sync(FULLM, ghB, nsrc);
        if (lane < HH) {
            float in = nlo ? s_iA : s_iB;
            float hn = nlo ? s_hA : s_hB;
            float r = sigf(giA + ghA);
            float z = sigf(giB + ghB);
            float n = tanhfast(fmaf(r, hn, in));
            hreg = tanhfast(fmaf(z, hreg - n, n));
        }
        dist_h(hreg);      // shfl convergence also orders xsh WAR vs do_fc stores
        do_fc(SS - 1 - t);
        __syncwarp();      // xsh RAW for next iteration
    }
}

extern "C" void kernel_launch(void* const* d_in, const int* in_sizes, int n_in,
                              void* d_out, int out_size) {
    const float* x    = (const float*)d_in[0];
    const int*   oneh = (const int*)d_in[1];
    const float* e0   = (const float*)d_in[2];
    const float* e1   = (const float*)d_in[3];
    const float* e2   = (const float*)d_in[4];
    const float* e3   = (const float*)d_in[5];
    const float* Wih1 = (const float*)d_in[6];
    const float* Whh1 = (const float*)d_in[7];
    const float* bih1 = (const float*)d_in[8];
    const float* bhh1 = (const float*)d_in[9];
    const float* Wih2 = (const float*)d_in[10];
    const float* Whh2 = (const float*)d_in[11];
    const float* bih2 = (const float*)d_in[12];
    const float* bhh2 = (const float*)d_in[13];
    const float* Wfc  = (const float*)d_in[14];
    const float* bfc  = (const float*)d_in[15];

    gruae_kernel<<<BB / NWARPS, NTHREADS>>>(
        x, oneh, e0, e1, e2, e3, Wih1, Whh1, bih1, bhh1,
        Wih2, Whh2, bih2, bhh2, Wfc, bfc, (float*)d_out);
}

// round 4
// speedup vs baseline: 1.1189x; 1.1189x over previous
#include <cuda_runtime.h>

// GruAeModel: B=1024, S=1024, F=36, H=20.
// Round 4: K1 (parallel) precomputes xin/origin + encoder input gates gi1 into
// 256MiB scratch; K2 (serial, warp-per-batch) runs recurrences with MUFU tanh.

#define HH 20
#define FF 36
#define RR 12
#define BB 1024
#define SS 1024
#define FULLM 0xffffffffu
#define DQ 6

typedef unsigned long long u64;

// gi scratch: [b][t][64]; lane l<30 owns slots l (gate gA) and 32+l (gate gB)
static __device__ float g_gi[(size_t)BB * SS * 64];

__device__ __forceinline__ u64 ffma2(u64 a, u64 b, u64 c) {
    u64 d;
    asm("fma.rn.f32x2 %0, %1, %2, %3;" : "=l"(d) : "l"(a), "l"(b), "l"(c));
    return d;
}
__device__ __forceinline__ u64 fadd2(u64 a, u64 b) {
    u64 d;
    asm("add.rn.f32x2 %0, %1, %2;" : "=l"(d) : "l"(a), "l"(b));
    return d;
}
__device__ __forceinline__ float fold2(u64 a) {
    float lo = __uint_as_float((unsigned)a);
    float hi = __uint_as_float((unsigned)(a >> 32));
    return lo + hi;
}
__device__ __forceinline__ float tanha(float x) {
    float y;
    asm("tanh.approx.f32 %0, %1;" : "=f"(y) : "f"(x));
    return y;
}
__device__ __forceinline__ float siga(float x) {
    return fmaf(0.5f, tanha(0.5f * x), 0.5f);
}

// gate mapping shared by K1/K2:
// lane<20: gA=row lane (r), gB=row 20+lane (z)
// lane 20+k (k<10): gA=row 40+k (n low), gB=row 50+k (n high)

// ===================== K1: xin build + origin + gi1 precompute =====================
// grid = 2048 blocks (128 b-groups x 16 time-chunks of 64), block = 256 (8 warps)
__global__ __launch_bounds__(256, 2) void k1_pregate(
    const float* __restrict__ x, const int* __restrict__ oneh,
    const float* __restrict__ e0t, const float* __restrict__ e1t,
    const float* __restrict__ e2t, const float* __restrict__ e3t,
    const float* __restrict__ Wih1, const float* __restrict__ bih1,
    float* __restrict__ out) {
    __shared__ __align__(16) float etab[1320];
    __shared__ __align__(16) float XT[8][40];

    const int tid = threadIdx.x;
    const int wid = tid >> 5;
    const int lane = tid & 31;

    for (int i = tid; i < 40; i += 256) etab[i] = e0t[i];
    for (int i = tid; i < 80; i += 256) etab[40 + i] = e1t[i];
    for (int i = tid; i < 400; i += 256) etab[120 + i] = e2t[i];
    for (int i = tid; i < 800; i += 256) etab[520 + i] = e3t[i];

    const int bg = blockIdx.x >> 4;
    const int ck = blockIdx.x & 15;
    const int b = bg * 8 + wid;
    const int t0 = ck * 64;
    float* const xsh = XT[wid];

    const int gA = (lane < 20) ? lane : lane + 20;
    const int gB = (lane < 20) ? lane + 20 : lane + 30;
    u64 wiA[18], wiB[18];
    float biA = 0.f, biB = 0.f;
    if (lane < 30) {
        const u64* ra = (const u64*)(Wih1 + gA * FF);
        const u64* rb = (const u64*)(Wih1 + gB * FF);
#pragma unroll
        for (int j = 0; j < 18; j++) { wiA[j] = ra[j]; wiB[j] = rb[j]; }
        biA = bih1[gA]; biB = bih1[gB];
    }
    __syncthreads();

    // streams
    const float* xptr = x + ((size_t)b * SS + t0) * RR + lane;
    const int* optr = oneh + ((size_t)b * SS + t0) * 4 + (lane - 12);
    float xq0 = 0.f, xq1 = 0.f, xq2 = 0.f;
    int oq0 = 0, oq1 = 0, oq2 = 0;
    if (lane < 12) {
        xq0 = xptr[0]; xq1 = xptr[RR]; xq2 = xptr[2 * RR]; xptr += 3 * RR;
    } else if (lane < 16) {
        oq0 = optr[0]; oq1 = optr[4]; oq2 = optr[8]; optr += 12;
    }
    const int ec = lane - 12;
    const int edim = (ec < 2) ? 4 : 8;
    const int eoff = (ec == 0) ? 12 : (ec == 1) ? 16 : (ec == 2) ? 20 : 28;
    const int etb = (ec == 0) ? 0 : (ec == 1) ? 40 : (ec == 2) ? 120 : 520;

    float* const origin = out + (size_t)b * SS * FF;
    float* const gout = g_gi + ((size_t)b * SS + t0) * 64;

    for (int u = 0; u < 64; u++) {
        const int t = t0 + u;
        if (lane < 12) {
            xsh[lane] = xq0;
        } else if (lane < 16) {
            const float* tb = etab + etb + oq0 * edim;
#pragma unroll
            for (int i = 0; i < 4; i++) xsh[eoff + i] = tb[i];
            if (edim == 8) {
#pragma unroll
                for (int i = 4; i < 8; i++) xsh[eoff + i] = tb[i];
            }
        }
        xq0 = xq1; xq1 = xq2; oq0 = oq1; oq1 = oq2;
        if (t + 3 < SS) {
            if (lane < 12)      { xq2 = xptr[0]; xptr += RR; }
            else if (lane < 16) { oq2 = optr[0]; optr += 4; }
        }
        __syncwarp();
        origin[(size_t)t * FF + lane] = xsh[lane];
        if (lane < 4) origin[(size_t)t * FF + 32 + lane] = xsh[32 + lane];
        if (lane < 30) {
            u64 a[2] = {0, 0}, bb[2] = {0, 0};
#pragma unroll
            for (int j = 0; j < 18; j++) {
                u64 xk = *(const u64*)(xsh + 2 * j);
                a[j & 1] = ffma2(wiA[j], xk, a[j & 1]);
                bb[j & 1] = ffma2(wiB[j], xk, bb[j & 1]);
            }
            gout[(size_t)u * 64 + lane] = fold2(fadd2(a[0], a[1])) + biA;
            gout[(size_t)u * 64 + 32 + lane] = fold2(fadd2(bb[0], bb[1])) + biB;
        }
        __syncwarp();
    }
}

// ===================== K2: encoder recurrence + decoder =====================
__global__ __launch_bounds__(256, 1) void k2_recur(
    const float* __restrict__ Whh1, const float* __restrict__ bhh1,
    const float* __restrict__ Wih2, const float* __restrict__ Whh2,
    const float* __restrict__ bih2, const float* __restrict__ bhh2,
    const float* __restrict__ Wfc, const float* __restrict__ bfc,
    float* __restrict__ out) {
    __shared__ __align__(16) float XS[8][40];
    __shared__ __align__(16) float HS[8][24];

    const int tid = threadIdx.x;
    const int wid = tid >> 5;
    const int lane = tid & 31;
    const int b = blockIdx.x * 8 + wid;
    float* const xsh = XS[wid];
    float* const hsh = HS[wid];

    const int gA = (lane < 20) ? lane : lane + 20;
    const int gB = (lane < 20) ? lane + 20 : lane + 30;
    const int nsrc = 20 + (lane % 10);
    const bool nlo = (lane < 10);

    // encoder weights: only Whh1
    u64 whA[10], whB[10];
    float bhA = 0.f, bhB = 0.f;
    if (lane < 30) {
        const u64* ha = (const u64*)(Whh1 + gA * HH);
        const u64* hb = (const u64*)(Whh1 + gB * HH);
#pragma unroll
        for (int j = 0; j < 10; j++) { whA[j] = ha[j]; whB[j] = hb[j]; }
        bhA = bhh1[gA]; bhB = bhh1[gB];
    }
    if (lane < HH) hsh[lane] = 0.f;

    // gi prefetch queue
    const float* const gin = g_gi + (size_t)b * SS * 64;
    float qA[DQ], qB[DQ];
#pragma unroll
    for (int d = 0; d < DQ; d++) {
        qA[d] = (lane < 30) ? gin[(size_t)d * 64 + lane] : 0.f;
        qB[d] = (lane < 30) ? gin[(size_t)d * 64 + 32 + lane] : 0.f;
    }
    float hreg = 0.f;
    __syncwarp();

    // ================= encoder =================
    for (int t = 0; t < SS; t++) {
        float ghA = 0.f, ghB = 0.f;
        if (lane < 30) {
            u64 a[2] = {0, 0}, bb[2] = {0, 0};
#pragma unroll
            for (int j = 0; j < 10; j++) {
                u64 hk = *(const u64*)(hsh + 2 * j);
                a[j & 1] = ffma2(whA[j], hk, a[j & 1]);
                bb[j & 1] = ffma2(whB[j], hk, bb[j & 1]);
            }
            ghA = fold2(fadd2(a[0], a[1])) + bhA;
            ghB = fold2(fadd2(bb[0], bb[1])) + bhB;
        }
        float giA = qA[0], giB = qB[0];
        float s_iA = __shfl_sync(FULLM, giA, nsrc);
        float s_iB = __shfl_sync(FULLM, giB, nsrc);
        float s_hA = __shfl_sync(FULLM, ghA, nsrc);
        float s_hB = __shfl_sync(FULLM, ghB, nsrc);
        if (lane < HH) {
            float in = nlo ? s_iA : s_iB;
            float hn = nlo ? s_hA : s_hB;
            float r = siga(giA + ghA);
            float z = siga(giB + ghB);
            float n = tanha(fmaf(r, hn, in));
            hreg = fmaf(z, hreg - n, n);
            hsh[lane] = hreg;
        }
        // rotate queue + prefetch t+DQ
#pragma unroll
        for (int d = 0; d < DQ - 1; d++) { qA[d] = qA[d + 1]; qB[d] = qB[d + 1]; }
        if (t + DQ < SS && lane < 30) {
            qA[DQ - 1] = gin[(size_t)(t + DQ) * 64 + lane];
            qB[DQ - 1] = gin[(size_t)(t + DQ) * 64 + 32 + lane];
        }
        __syncwarp();
    }

    // ---- handoff + decoder weights ----
    if (lane < HH) { hreg = tanha(hreg); hsh[lane] = hreg; }
    u64 wiA[18], wiB[18];
    float biA = 0.f, biB = 0.f;
    if (lane < 30) {
        const u64* ra = (const u64*)(Wih2 + gA * FF);
        const u64* rb = (const u64*)(Wih2 + gB * FF);
#pragma unroll
        for (int j = 0; j < 18; j++) { wiA[j] = ra[j]; wiB[j] = rb[j]; }
        const u64* ha = (const u64*)(Whh2 + gA * HH);
        const u64* hb = (const u64*)(Whh2 + gB * HH);
#pragma unroll
        for (int j = 0; j < 10; j++) { whA[j] = ha[j]; whB[j] = hb[j]; }
        biA = bih2[gA]; biB = bih2[gB]; bhA = bhh2[gA]; bhB = bhh2[gB];
    }
    u64 wf0[10], wf1[10];
    float bf0 = 0.f, bf1 = 0.f;
    if (lane < 18) {
        const u64* f0 = (const u64*)(Wfc + (2 * lane) * HH);
        const u64* f1 = (const u64*)(Wfc + (2 * lane + 1) * HH);
#pragma unroll
        for (int j = 0; j < 10; j++) { wf0[j] = f0[j]; wf1[j] = f1[j]; }
        bf0 = bfc[2 * lane]; bf1 = bfc[2 * lane + 1];
    }
    float* const xsout = out + (size_t)(BB + b) * SS * FF;
    __syncwarp();

    // t=0 FC: x0 = tanh(Wfc h + bfc)
    if (lane < 18) {
        u64 a0[2] = {0, 0}, a1[2] = {0, 0};
#pragma unroll
        for (int j = 0; j < 10; j++) {
            u64 hk = *(const u64*)(hsh + 2 * j);
            a0[j & 1] = ffma2(wf0[j], hk, a0[j & 1]);
            a1[j & 1] = ffma2(wf1[j], hk, a1[j & 1]);
        }
        float v0 = tanha(fold2(fadd2(a0[0], a0[1])) + bf0);
        float v1 = tanha(fold2(fadd2(a1[0], a1[1])) + bf1);
        *(float2*)(xsh + 2 * lane) = make_float2(v0, v1);
        *(float2*)(xsout + (size_t)(SS - 1) * FF + 2 * lane) = make_float2(v0, v1);
    }
    __syncwarp();

    // ================= decoder =================
    for (int t = 1; t < SS; t++) {
        float giA = 0.f, giB = 0.f, ghA = 0.f, ghB = 0.f;
        if (lane < 30) {
            u64 ai[2] = {0, 0}, bi[2] = {0, 0}, ah[2] = {0, 0}, bh[2] = {0, 0};
#pragma unroll
            for (int j = 0; j < 18; j++) {
                u64 xk = *(const u64*)(xsh + 2 * j);
                ai[j & 1] = ffma2(wiA[j], xk, ai[j & 1]);
                bi[j & 1] = ffma2(wiB[j], xk, bi[j & 1]);
            }
#pragma unroll
            for (int j = 0; j < 10; j++) {
                u64 hk = *(const u64*)(hsh + 2 * j);
                ah[j & 1] = ffma2(whA[j], hk, ah[j & 1]);
                bh[j & 1] = ffma2(whB[j], hk, bh[j & 1]);
            }
            giA = fold2(fadd2(ai[0], ai[1])) + biA;
            giB = fold2(fadd2(bi[0], bi[1])) + biB;
            ghA = fold2(fadd2(ah[0], ah[1])) + bhA;
            ghB = fold2(fadd2(bh[0], bh[1])) + bhB;
        }
        float s_iA = __shfl_sync(FULLM, giA, nsrc);
        float s_iB = __shfl_sync(FULLM, giB, nsrc);
        float s_hA = __shfl_sync(FULLM, ghA, nsrc);
        float s_hB = __shfl_sync(FULLM, ghB, nsrc);
        if (lane < HH) {
            float in = nlo ? s_iA : s_iB;
            float hn = nlo ? s_hA : s_hB;
            float r = siga(giA + ghA);
            float z = siga(giB + ghB);
            float n = tanha(fmaf(r, hn, in));
            hreg = tanha(fmaf(z, hreg - n, n));
            hsh[lane] = hreg;
        }
        __syncwarp();
        if (lane < 18) {
            u64 a0[2] = {0, 0}, a1[2] = {0, 0};
#pragma unroll
            for (int j = 0; j < 10; j++) {
                u64 hk = *(const u64*)(hsh + 2 * j);
                a0[j & 1] = ffma2(wf0[j], hk, a0[j & 1]);
                a1[j & 1] = ffma2(wf1[j], hk, a1[j & 1]);
            }
            float v0 = tanha(fold2(fadd2(a0[0], a0[1])) + bf0);
            float v1 = tanha(fold2(fadd2(a1[0], a1[1])) + bf1);
            *(float2*)(xsh + 2 * lane) = make_float2(v0, v1);
            size_t row = (size_t)(SS - 1 - t) * FF + 2 * lane;
            *(float2*)(xsout + row) = make_float2(v0, v1);
        }
        __syncwarp();
    }
}

extern "C" void kernel_launch(void* const* d_in, const int* in_sizes, int n_in,
                              void* d_out, int out_size) {
    const float* x    = (const float*)d_in[0];
    const int*   oneh = (const int*)d_in[1];
    const float* e0   = (const float*)d_in[2];
    const float* e1   = (const float*)d_in[3];
    const float* e2   = (const float*)d_in[4];
    const float* e3   = (const float*)d_in[5];
    const float* Wih1 = (const float*)d_in[6];
    const float* Whh1 = (const float*)d_in[7];
    const float* bih1 = (const float*)d_in[8];
    const float* bhh1 = (const float*)d_in[9];
    const float* Wih2 = (const float*)d_in[10];
    const float* Whh2 = (const float*)d_in[11];
    const float* bih2 = (const float*)d_in[12];
    const float* bhh2 = (const float*)d_in[13];
    const float* Wfc  = (const float*)d_in[14];
    const float* bfc  = (const float*)d_in[15];
    float* out = (float*)d_out;

    k1_pregate<<<2048, 256>>>(x, oneh, e0, e1, e2, e3, Wih1, bih1, out);
    k2_recur<<<128, 256>>>(Whh1, bhh1, Wih2, Whh2, bih2, bhh2, Wfc, bfc, out);
}

// round 5
// speedup vs baseline: 1.3095x; 1.1703x over previous
#include <cuda_runtime.h>

// GruAeModel: B=1024, S=1024, F=36, H=20.
// Round 5: branch-free lanes. All-lane compute with clamped weight rows;
// only single predicated stores remain. K1: 1 sync/iter via parity x-tile.

#define HH 20
#define FF 36
#define RR 12
#define BB 1024
#define SS 1024
#define FULLM 0xffffffffu
#define DQ 6

typedef unsigned long long u64;

// gi scratch: [b][t][64]; slots l and 32+l (l<32; 30,31 are junk lanes)
static __device__ float g_gi[(size_t)BB * SS * 64];

__device__ __forceinline__ u64 ffma2(u64 a, u64 b, u64 c) {
    u64 d;
    asm("fma.rn.f32x2 %0, %1, %2, %3;" : "=l"(d) : "l"(a), "l"(b), "l"(c));
    return d;
}
__device__ __forceinline__ u64 fadd2(u64 a, u64 b) {
    u64 d;
    asm("add.rn.f32x2 %0, %1, %2;" : "=l"(d) : "l"(a), "l"(b));
    return d;
}
__device__ __forceinline__ float fold2(u64 a) {
    float lo = __uint_as_float((unsigned)a);
    float hi = __uint_as_float((unsigned)(a >> 32));
    return lo + hi;
}
__device__ __forceinline__ float tanha(float x) {
    float y;
    asm("tanh.approx.f32 %0, %1;" : "=f"(y) : "f"(x));
    return y;
}
__device__ __forceinline__ float siga(float x) {
    return fmaf(0.5f, tanha(0.5f * x), 0.5f);
}
__device__ __forceinline__ int imin(int a, int b) { return a < b ? a : b; }

// gate mapping: lane<20: gA=row lane (r), gB=row 20+lane (z)
// lane 20+k (k<10): gA=row 40+k (n lo), gB=row 50+k (n hi); lanes 30,31 junk.

// ===================== K1: xin build + origin + gi1 precompute =====================
__global__ __launch_bounds__(256, 2) void k1_pregate(
    const float* __restrict__ x, const int* __restrict__ oneh,
    const float* __restrict__ e0t, const float* __restrict__ e1t,
    const float* __restrict__ e2t, const float* __restrict__ e3t,
    const float* __restrict__ Wih1, const float* __restrict__ bih1,
    float* __restrict__ out) {
    __shared__ __align__(16) float etab[1320];
    __shared__ __align__(16) float XT[8][2][40];

    const int tid = threadIdx.x;
    const int wid = tid >> 5;
    const int lane = tid & 31;

    for (int i = tid; i < 40; i += 256) etab[i] = e0t[i];
    for (int i = tid; i < 80; i += 256) etab[40 + i] = e1t[i];
    for (int i = tid; i < 400; i += 256) etab[120 + i] = e2t[i];
    for (int i = tid; i < 800; i += 256) etab[520 + i] = e3t[i];

    const int bg = blockIdx.x >> 4;
    const int ck = blockIdx.x & 15;
    const int b = bg * 8 + wid;
    const int t0 = ck * 64;

    const int gA = (lane < 20) ? lane : lane + 20;            // <= 51, valid
    const int gB = imin((lane < 20) ? lane + 20 : lane + 30, 59);
    u64 wiA[18], wiB[18];
    const u64* ra = (const u64*)(Wih1 + gA * FF);
    const u64* rb = (const u64*)(Wih1 + gB * FF);
#pragma unroll
    for (int j = 0; j < 18; j++) { wiA[j] = ra[j]; wiB[j] = rb[j]; }
    float biA = bih1[gA], biB = bih1[gB];
    __syncthreads();

    // per-lane feature-map constants
    const int osrc = (lane < 16) ? 12 : (lane < 20) ? 13 : (lane < 28) ? 14 : 15;
    const int tscale = (lane < 20) ? 4 : 8;
    const int tadd = ((lane < 16) ? (0 - 12) : (lane < 20) ? (40 - 16)
                      : (lane < 28) ? (120 - 20) : (520 - 28)) + lane;

    // streams: lanes 0-11 raw x col, 12-15 onehot col
    float xq0 = 0.f, xq1 = 0.f, xq2 = 0.f;
    int oq0 = 0, oq1 = 0, oq2 = 0;
    {
        const float* xptr = x + ((size_t)b * SS + t0) * RR + lane;
        const int* optr = oneh + ((size_t)b * SS + t0) * 4 + (lane - 12);
        if (lane < 12) { xq0 = xptr[0]; xq1 = xptr[RR]; xq2 = xptr[2 * RR]; }
        else if (lane < 16) { oq0 = optr[0]; oq1 = optr[4]; oq2 = optr[8]; }
    }

    float* const origin = out + (size_t)b * SS * FF;
    float* const gout = g_gi + ((size_t)b * SS + t0) * 64;

    for (int u = 0; u < 64; u++) {
        const int t = t0 + u;
        // build xin (branch-free): o via one shfl, 1 LDS per lane
        int o = __shfl_sync(FULLM, oq0, osrc);
        int o3 = __shfl_sync(FULLM, oq0, 15);
        float ev = etab[tadd + o * tscale];
        float v = (lane < 12) ? xq0 : ev;
        float* const xc = XT[wid][u & 1];
        xc[lane] = v;
        origin[(size_t)t * FF + lane] = v;
        if (lane < 4) {
            float v2 = etab[520 + o3 * 8 + (lane + 4)];
            xc[32 + lane] = v2;
            origin[(size_t)t * FF + 32 + lane] = v2;
        }
        // rotate + prefetch t+3 (clamped, predicated single loads)
        xq0 = xq1; xq1 = xq2; oq0 = oq1; oq1 = oq2;
        {
            const int tn = imin(t + 3, SS - 1);
            if (lane < 12)
                xq2 = x[((size_t)b * SS + tn) * RR + lane];
            else if (lane < 16)
                oq2 = oneh[((size_t)b * SS + tn) * 4 + (lane - 12)];
        }
        __syncwarp();
        // matvec (all lanes), 4-way acc
        u64 a[2] = {0, 0}, bb[2] = {0, 0}, a2[2] = {0, 0}, bb2[2] = {0, 0};
#pragma unroll
        for (int j = 0; j < 18; j += 2) {
            u64 xk0 = *(const u64*)(xc + 2 * j);
            u64 xk1 = *(const u64*)(xc + 2 * j + 2);
            a[0] = ffma2(wiA[j], xk0, a[0]);
            bb[0] = ffma2(wiB[j], xk0, bb[0]);
            a2[0] = ffma2(wiA[j + 1], xk1, a2[0]);
            bb2[0] = ffma2(wiB[j + 1], xk1, bb2[0]);
        }
        gout[(size_t)u * 64 + lane] = fold2(fadd2(a[0], a2[0])) + biA;
        gout[(size_t)u * 64 + 32 + lane] = fold2(fadd2(bb[0], bb2[0])) + biB;
        // parity x-tile: no second sync needed
    }
}

// ===================== K2: encoder recurrence + decoder =====================
__global__ __launch_bounds__(256, 1) void k2_recur(
    const float* __restrict__ Whh1, const float* __restrict__ bhh1,
    const float* __restrict__ Wih2, const float* __restrict__ Whh2,
    const float* __restrict__ bih2, const float* __restrict__ bhh2,
    const float* __restrict__ Wfc, const float* __restrict__ bfc,
    float* __restrict__ out) {
    __shared__ __align__(16) float XS[8][40];
    __shared__ __align__(16) float HS[8][24];

    const int tid = threadIdx.x;
    const int wid = tid >> 5;
    const int lane = tid & 31;
    const int b = blockIdx.x * 8 + wid;
    float* const xsh = XS[wid];
    float* const hsh = HS[wid];

    const int gA = (lane < 20) ? lane : lane + 20;
    const int gB = imin((lane < 20) ? lane + 20 : lane + 30, 59);
    const int nsrc = 20 + (lane % 10);
    const bool nlo = (lane < 10);

    // encoder: Whh1 only (all lanes)
    u64 whA[10], whB[10];
    {
        const u64* ha = (const u64*)(Whh1 + gA * HH);
        const u64* hb = (const u64*)(Whh1 + gB * HH);
#pragma unroll
        for (int j = 0; j < 10; j++) { whA[j] = ha[j]; whB[j] = hb[j]; }
    }
    float bhA = bhh1[gA], bhB = bhh1[gB];
    if (lane < 24) hsh[lane] = 0.f;

    // gi prefetch queue (all lanes; slots lane, 32+lane in-bounds)
    const float* const gin = g_gi + (size_t)b * SS * 64;
    float qA[DQ], qB[DQ];
#pragma unroll
    for (int d = 0; d < DQ; d++) {
        qA[d] = gin[(size_t)d * 64 + lane];
        qB[d] = gin[(size_t)d * 64 + 32 + lane];
    }
    float hreg = 0.f;
    __syncwarp();

    // ================= encoder =================
    for (int t = 0; t < SS; t++) {
        u64 a[2] = {0, 0}, bb[2] = {0, 0};
#pragma unroll
        for (int j = 0; j < 10; j++) {
            u64 hk = *(const u64*)(hsh + 2 * j);
            a[j & 1] = ffma2(whA[j], hk, a[j & 1]);
            bb[j & 1] = ffma2(whB[j], hk, bb[j & 1]);
        }
        float ghA = fold2(fadd2(a[0], a[1])) + bhA;
        float ghB = fold2(fadd2(bb[0], bb[1])) + bhB;
        float giA = qA[0], giB = qB[0];
        float s_iA = __shfl_sync(FULLM, giA, nsrc);
        float s_iB = __shfl_sync(FULLM, giB, nsrc);
        float s_hA = __shfl_sync(FULLM, ghA, nsrc);
        float s_hB = __shfl_sync(FULLM, ghB, nsrc);
        float in = nlo ? s_iA : s_iB;
        float hn = nlo ? s_hA : s_hB;
        float r = siga(giA + ghA);
        float z = siga(giB + ghB);
        float n = tanha(fmaf(r, hn, in));
        hreg = fmaf(z, hreg - n, n);
        if (lane < HH) hsh[lane] = hreg;
        // rotate + prefetch (unconditional, clamped)
#pragma unroll
        for (int d = 0; d < DQ - 1; d++) { qA[d] = qA[d + 1]; qB[d] = qB[d + 1]; }
        {
            const size_t tp = (size_t)imin(t + DQ, SS - 1) * 64;
            qA[DQ - 1] = gin[tp + lane];
            qB[DQ - 1] = gin[tp + 32 + lane];
        }
        __syncwarp();
    }

    // ---- handoff + decoder weights (all lanes, clamped rows) ----
    hreg = tanha(hreg);
    if (lane < HH) hsh[lane] = hreg;
    u64 wiA[18], wiB[18];
    {
        const u64* ra = (const u64*)(Wih2 + gA * FF);
        const u64* rb = (const u64*)(Wih2 + gB * FF);
#pragma unroll
        for (int j = 0; j < 18; j++) { wiA[j] = ra[j]; wiB[j] = rb[j]; }
        const u64* ha = (const u64*)(Whh2 + gA * HH);
        const u64* hb = (const u64*)(Whh2 + gB * HH);
#pragma unroll
        for (int j = 0; j < 10; j++) { whA[j] = ha[j]; whB[j] = hb[j]; }
    }
    float biA = bih2[gA], biB = bih2[gB];
    bhA = bhh2[gA]; bhB = bhh2[gB];
    u64 wf0[10], wf1[10];
    const int fr0 = (lane < 18) ? 2 * lane : 0;
    const int fr1 = (lane < 18) ? 2 * lane + 1 : 0;
    {
        const u64* f0 = (const u64*)(Wfc + fr0 * HH);
        const u64* f1 = (const u64*)(Wfc + fr1 * HH);
#pragma unroll
        for (int j = 0; j < 10; j++) { wf0[j] = f0[j]; wf1[j] = f1[j]; }
    }
    float bf0 = bfc[fr0], bf1 = bfc[fr1];
    float* const xsout = out + (size_t)(BB + b) * SS * FF;
    __syncwarp();

    // t=0 FC (all lanes compute, predicated stores)
    {
        u64 a0[2] = {0, 0}, a1[2] = {0, 0};
#pragma unroll
        for (int j = 0; j < 10; j++) {
            u64 hk = *(const u64*)(hsh + 2 * j);
            a0[j & 1] = ffma2(wf0[j], hk, a0[j & 1]);
            a1[j & 1] = ffma2(wf1[j], hk, a1[j & 1]);
        }
        float v0 = tanha(fold2(fadd2(a0[0], a0[1])) + bf0);
        float v1 = tanha(fold2(fadd2(a1[0], a1[1])) + bf1);
        if (lane < 18) {
            *(float2*)(xsh + 2 * lane) = make_float2(v0, v1);
            *(float2*)(xsout + (size_t)(SS - 1) * FF + 2 * lane) = make_float2(v0, v1);
        }
    }
    __syncwarp();

    // ================= decoder =================
    for (int t = 1; t < SS; t++) {
        u64 ai[4] = {0, 0, 0, 0}, bi[4] = {0, 0, 0, 0};
        u64 ah[2] = {0, 0}, bh[2] = {0, 0};
#pragma unroll
        for (int j = 0; j < 18; j += 2) {
            u64 xk0 = *(const u64*)(xsh + 2 * j);
            u64 xk1 = *(const u64*)(xsh + 2 * j + 2);
            ai[0] = ffma2(wiA[j], xk0, ai[0]);
            bi[0] = ffma2(wiB[j], xk0, bi[0]);
            ai[1] = ffma2(wiA[j + 1], xk1, ai[1]);
            bi[1] = ffma2(wiB[j + 1], xk1, bi[1]);
        }
#pragma unroll
        for (int j = 0; j < 10; j++) {
            u64 hk = *(const u64*)(hsh + 2 * j);
            ah[j & 1] = ffma2(whA[j], hk, ah[j & 1]);
            bh[j & 1] = ffma2(whB[j], hk, bh[j & 1]);
        }
        float giA = fold2(fadd2(ai[0], ai[1])) + biA;
        float giB = fold2(fadd2(bi[0], bi[1])) + biB;
        float ghA = fold2(fadd2(ah[0], ah[1])) + bhA;
        float ghB = fold2(fadd2(bh[0], bh[1])) + bhB;
        float s_iA = __shfl_sync(FULLM, giA, nsrc);
        float s_iB = __shfl_sync(FULLM, giB, nsrc);
        float s_hA = __shfl_sync(FULLM, ghA, nsrc);
        float s_hB = __shfl_sync(FULLM, ghB, nsrc);
        float in = nlo ? s_iA : s_iB;
        float hn = nlo ? s_hA : s_hB;
        float r = siga(giA + ghA);
        float z = siga(giB + ghB);
        float n = tanha(fmaf(r, hn, in));
        hreg = tanha(fmaf(z, hreg - n, n));
        if (lane < HH) hsh[lane] = hreg;
        __syncwarp();
        // FC (all lanes compute, predicated stores)
        u64 a0[2] = {0, 0}, a1[2] = {0, 0};
#pragma unroll
        for (int j = 0; j < 10; j++) {
            u64 hk = *(const u64*)(hsh + 2 * j);
            a0[j & 1] = ffma2(wf0[j], hk, a0[j & 1]);
            a1[j & 1] = ffma2(wf1[j], hk, a1[j & 1]);
        }
        float v0 = tanha(fold2(fadd2(a0[0], a0[1])) + bf0);
        float v1 = tanha(fold2(fadd2(a1[0], a1[1])) + bf1);
        if (lane < 18) {
            *(float2*)(xsh + 2 * lane) = make_float2(v0, v1);
            size_t row = (size_t)(SS - 1 - t) * FF + 2 * lane;
            *(float2*)(xsout + row) = make_float2(v0, v1);
        }
        __syncwarp();
    }
}

extern "C" void kernel_launch(void* const* d_in, const int* in_sizes, int n_in,
                              void* d_out, int out_size) {
    const float* x    = (const float*)d_in[0];
    const int*   oneh = (const int*)d_in[1];
    const float* e0   = (const float*)d_in[2];
    const float* e1   = (const float*)d_in[3];
    const float* e2   = (const float*)d_in[4];
    const float* e3   = (const float*)d_in[5];
    const float* Wih1 = (const float*)d_in[6];
    const float* Whh1 = (const float*)d_in[7];
    const float* bih1 = (const float*)d_in[8];
    const float* bhh1 = (const float*)d_in[9];
    const float* Wih2 = (const float*)d_in[10];
    const float* Whh2 = (const float*)d_in[11];
    const float* bih2 = (const float*)d_in[12];
    const float* bhh2 = (const float*)d_in[13];
    const float* Wfc  = (const float*)d_in[14];
    const float* bfc  = (const float*)d_in[15];
    float* out = (float*)d_out;

    k1_pregate<<<2048, 256>>>(x, oneh, e0, e1, e2, e3, Wih1, bih1, out);
    k2_recur<<<128, 256>>>(Whh1, bhh1, Wih2, Whh2, bih2, bhh2, Wfc, bfc, out);
}

// round 6
// speedup vs baseline: 1.6588x; 1.2668x over previous
#include <cuda_runtime.h>

// GruAeModel: B=1024, S=1024, F=36, H=20.
// Round 6: fully branch-free hot loops (no BSSY, no WARPSYNC — converged-warp
// smem ordering + compiler barriers). Decoder loads h once/step (FC + carried
// gh matvec). K1: 1 weight row/lane, 2 warps/stream, occupancy 3 blocks/SM.

#define HH 20
#define FF 36
#define RR 12
#define BB 1024
#define SS 1024
#define FULLM 0xffffffffu
#define DQ 8

typedef unsigned long long u64;

// gi scratch: [b][t][64]; slots l (gA rows) and 32+l (gB rows); 30,31,62,63 junk
static __device__ float g_gi[(size_t)BB * SS * 64];

#define CBAR() asm volatile("" ::: "memory")

__device__ __forceinline__ u64 ffma2(u64 a, u64 b, u64 c) {
    u64 d;
    asm("fma.rn.f32x2 %0, %1, %2, %3;" : "=l"(d) : "l"(a), "l"(b), "l"(c));
    return d;
}
__device__ __forceinline__ u64 fadd2(u64 a, u64 b) {
    u64 d;
    asm("add.rn.f32x2 %0, %1, %2;" : "=l"(d) : "l"(a), "l"(b));
    return d;
}
__device__ __forceinline__ float fold2(u64 a) {
    float lo = __uint_as_float((unsigned)a);
    float hi = __uint_as_float((unsigned)(a >> 32));
    return lo + hi;
}
__device__ __forceinline__ u64 pack2(float lo, float hi) {
    u64 d;
    asm("mov.b64 %0, {%1, %2};" : "=l"(d) : "f"(lo), "f"(hi));
    return d;
}
__device__ __forceinline__ float tanha(float x) {
    float y;
    asm("tanh.approx.f32 %0, %1;" : "=f"(y) : "f"(x));
    return y;
}
__device__ __forceinline__ float siga(float x) {
    return fmaf(0.5f, tanha(0.5f * x), 0.5f);
}
__device__ __forceinline__ int imin(int a, int b) { return a < b ? a : b; }

__device__ __forceinline__ void stg_pred(int p, float* addr, float v) {
    asm volatile("{.reg .pred q; setp.ne.s32 q, %0, 0; @q st.global.f32 [%1], %2;}"
                 :: "r"(p), "l"(addr), "f"(v));
}
__device__ __forceinline__ void stg2_pred(int p, float* addr, float v0, float v1) {
    asm volatile("{.reg .pred q; setp.ne.s32 q, %0, 0; @q st.global.v2.f32 [%1], {%2,%3};}"
                 :: "r"(p), "l"(addr), "f"(v0), "f"(v1));
}

// gate mapping: lane<20: gA=row lane (r), gB=row 20+lane (z)
// lane 20+k (k<10): gA=row 40+k (n lo), gB=row 50+k (n hi); lanes 30,31 junk.

// ===================== K1: xin build + origin + gi1 precompute =====================
// grid = 4096 (256 b-groups of 4 x 16 t-chunks of 64); warp pair per (b,chunk).
__global__ __launch_bounds__(256, 3) void k1_pregate(
    const float* __restrict__ x, const int* __restrict__ oneh,
    const float* __restrict__ e0t, const float* __restrict__ e1t,
    const float* __restrict__ e2t, const float* __restrict__ e3t,
    const float* __restrict__ Wih1, const float* __restrict__ bih1,
    float* __restrict__ out) {
    __shared__ __align__(16) float etab[1320];
    __shared__ __align__(16) float XT[8][64];

    const int tid = threadIdx.x;
    const int wid = tid >> 5;
    const int lane = tid & 31;

    for (int i = tid; i < 40; i += 256) etab[i] = e0t[i];
    for (int i = tid; i < 80; i += 256) etab[40 + i] = e1t[i];
    for (int i = tid; i < 400; i += 256) etab[120 + i] = e2t[i];
    for (int i = tid; i < 800; i += 256) etab[520 + i] = e3t[i];

    const int p = wid & 1;                       // which half of the 60 rows
    const int b = (blockIdx.x >> 4) * 4 + (wid >> 1);
    const int t0 = (blockIdx.x & 15) * 64;

    // one weight row per lane
    const int row = imin((lane < 20) ? lane + p * 20 : lane + 20 + p * 10, 59);
    u64 wi[18];
    {
        const u64* r = (const u64*)(Wih1 + row * FF);
#pragma unroll
        for (int j = 0; j < 18; j++) wi[j] = r[j];
    }
    const float bi = bih1[row];
    __syncthreads();

    // feature map constants
    const int osrc = (lane < 16) ? 12 : (lane < 20) ? 13 : (lane < 28) ? 14 : 15;
    const int tscale = (lane < 20) ? 4 : 8;
    const int tadd = ((lane < 16) ? (0 - 12) : (lane < 20) ? (40 - 16)
                      : (lane < 28) ? (120 - 20) : (520 - 28)) + lane;

    // unified input stream: lanes<12 raw x, lanes 12..15 onehot, 16+ dup of 15
    const int lc = imin(lane, 15);
    const unsigned* up = (lc < 12)
        ? (const unsigned*)(x + ((size_t)b * SS + t0) * RR + lc)
        : (const unsigned*)(oneh + ((size_t)b * SS + t0) * 4 + (lc - 12));
    const int stride = (lc < 12) ? RR : 4;
    unsigned q0 = up[0], q1 = up[stride], q2 = up[2 * stride];

    float* const origin = out + (size_t)b * SS * FF;
    float* const gout = g_gi + ((size_t)b * SS + t0) * 64 + p * 32 + lane;
    float* const xc = XT[wid];
    const int predMain = (p == 0);
    const int predExtra = (p == 1) && (lane < 4);

    for (int u = 0; u < 64; u++) {
        int o = __shfl_sync(FULLM, (int)q0, osrc);
        int o3 = __shfl_sync(FULLM, (int)q0, 15);
        float ev = etab[tadd + o * tscale];
        float v = (lane < 12) ? __uint_as_float(q0) : ev;
        float v2 = etab[520 + o3 * 8 + 4 + (lane & 3)];
        q0 = q1; q1 = q2;
        q2 = up[(size_t)imin(u + 3, 63) * stride];
        xc[lane] = v;
        xc[32 + lane] = v2;
        stg_pred(predMain, origin + (size_t)(t0 + u) * FF + lane, v);
        stg_pred(predExtra, origin + (size_t)(t0 + u) * FF + 32 + (lane & 3), v2);
        CBAR();
        u64 a0 = pack2(bi, 0.f), a1 = 0;
#pragma unroll
        for (int j = 0; j < 18; j += 2) {
            u64 xk0 = *(const u64*)(xc + 2 * j);
            u64 xk1 = *(const u64*)(xc + 2 * j + 2);
            a0 = ffma2(wi[j], xk0, a0);
            a1 = ffma2(wi[j + 1], xk1, a1);
        }
        gout[(size_t)u * 64] = fold2(fadd2(a0, a1));
        CBAR();
    }
}

// ===================== K2: encoder recurrence + decoder =====================
__global__ __launch_bounds__(256, 1) void k2_recur(
    const float* __restrict__ Whh1, const float* __restrict__ bhh1,
    const float* __restrict__ Wih2, const float* __restrict__ Whh2,
    const float* __restrict__ bih2, const float* __restrict__ bhh2,
    const float* __restrict__ Wfc, const float* __restrict__ bfc,
    float* __restrict__ out) {
    __shared__ __align__(16) float XS[8][64];   // x exchange, padded (junk 36..63)
    __shared__ __align__(16) float HS[8][32];   // h, padded (junk 20..31)

    const int tid = threadIdx.x;
    const int wid = tid >> 5;
    const int lane = tid & 31;
    const int b = blockIdx.x * 8 + wid;
    float* const xsh = XS[wid];
    float* const hsh = HS[wid];

    const int gA = (lane < 20) ? lane : lane + 20;
    const int gB = imin((lane < 20) ? lane + 20 : lane + 30, 59);
    const int nsrc = 20 + (lane % 10);
    const bool nlo = (lane < 10);

    u64 whA[10], whB[10];
    {
        const u64* ha = (const u64*)(Whh1 + gA * HH);
        const u64* hb = (const u64*)(Whh1 + gB * HH);
#pragma unroll
        for (int j = 0; j < 10; j++) { whA[j] = ha[j]; whB[j] = hb[j]; }
    }
    float bhA = bhh1[gA], bhB = bhh1[gB];
    hsh[lane] = 0.f;

    const float* const gin = g_gi + (size_t)b * SS * 64;
    float qA[DQ], qB[DQ];
#pragma unroll
    for (int d = 0; d < DQ; d++) {
        qA[d] = gin[(size_t)d * 64 + lane];
        qB[d] = gin[(size_t)d * 64 + 32 + lane];
    }
    float hreg = 0.f;
    CBAR();

    // ================= encoder =================
    for (int tb = 0; tb < SS; tb += DQ) {
#pragma unroll
        for (int d = 0; d < DQ; d++) {
            const int t = tb + d;
            u64 a0 = pack2(bhA, 0.f), a1 = 0, c0 = pack2(bhB, 0.f), c1 = 0;
#pragma unroll
            for (int j = 0; j < 10; j += 2) {
                u64 hk0 = *(const u64*)(hsh + 2 * j);
                u64 hk1 = *(const u64*)(hsh + 2 * j + 2);
                a0 = ffma2(whA[j], hk0, a0);
                a1 = ffma2(whA[j + 1], hk1, a1);
                c0 = ffma2(whB[j], hk0, c0);
                c1 = ffma2(whB[j + 1], hk1, c1);
            }
            float ghA = fold2(fadd2(a0, a1));
            float ghB = fold2(fadd2(c0, c1));
            float giA = qA[d], giB = qB[d];
            float s_iA = __shfl_sync(FULLM, giA, nsrc);
            float s_iB = __shfl_sync(FULLM, giB, nsrc);
            float s_hA = __shfl_sync(FULLM, ghA, nsrc);
            float s_hB = __shfl_sync(FULLM, ghB, nsrc);
            float in = nlo ? s_iA : s_iB;
            float hn = nlo ? s_hA : s_hB;
            float r = siga(giA + ghA);
            float z = siga(giB + ghB);
            float n = tanha(fmaf(r, hn, in));
            hreg = fmaf(z, hreg - n, n);
            hsh[lane] = hreg;
            CBAR();
            const size_t tp = (size_t)imin(t + DQ, SS - 1) * 64;
            qA[d] = gin[tp + lane];
            qB[d] = gin[tp + 32 + lane];
        }
    }

    // ---- handoff + decoder weights ----
    hreg = tanha(hreg);
    hsh[lane] = hreg;
    u64 wiA[18], wiB[18];
    {
        const u64* ra = (const u64*)(Wih2 + gA * FF);
        const u64* rb = (const u64*)(Wih2 + gB * FF);
#pragma unroll
        for (int j = 0; j < 18; j++) { wiA[j] = ra[j]; wiB[j] = rb[j]; }
        const u64* ha = (const u64*)(Whh2 + gA * HH);
        const u64* hb = (const u64*)(Whh2 + gB * HH);
#pragma unroll
        for (int j = 0; j < 10; j++) { whA[j] = ha[j]; whB[j] = hb[j]; }
    }
    const float biA = bih2[gA], biB = bih2[gB];
    bhA = bhh2[gA]; bhB = bhh2[gB];
    u64 wf0[10], wf1[10];
    const int fr0 = (lane < 18) ? 2 * lane : 0;
    const int fr1 = (lane < 18) ? 2 * lane + 1 : 0;
    {
        const u64* f0 = (const u64*)(Wfc + fr0 * HH);
        const u64* f1 = (const u64*)(Wfc + fr1 * HH);
#pragma unroll
        for (int j = 0; j < 10; j++) { wf0[j] = f0[j]; wf1[j] = f1[j]; }
    }
    const float bf0 = bfc[fr0], bf1 = bfc[fr1];
    float* const xsout = out + (size_t)(BB + b) * SS * FF;
    const int predX = (lane < 18);
    CBAR();

    // t=0: load hk once; FC -> x0; gh matvec carried into loop
    float ghAc, ghBc;
    {
        u64 hk[10];
#pragma unroll
        for (int j = 0; j < 10; j++) hk[j] = *(const u64*)(hsh + 2 * j);
        u64 f0a = pack2(bf0, 0.f), f0b = 0, f1a = pack2(bf1, 0.f), f1b = 0;
#pragma unroll
        for (int j = 0; j < 10; j += 2) {
            f0a = ffma2(wf0[j], hk[j], f0a);
            f0b = ffma2(wf0[j + 1], hk[j + 1], f0b);
            f1a = ffma2(wf1[j], hk[j], f1a);
            f1b = ffma2(wf1[j + 1], hk[j + 1], f1b);
        }
        float v0 = tanha(fold2(fadd2(f0a, f0b)));
        float v1 = tanha(fold2(fadd2(f1a, f1b)));
        *(float2*)(xsh + 2 * lane) = make_float2(v0, v1);
        stg2_pred(predX, xsout + (size_t)(SS - 1) * FF + 2 * lane, v0, v1);
        u64 a0 = pack2(bhA, 0.f), a1 = 0, c0 = pack2(bhB, 0.f), c1 = 0;
#pragma unroll
        for (int j = 0; j < 10; j += 2) {
            a0 = ffma2(whA[j], hk[j], a0);
            a1 = ffma2(whA[j + 1], hk[j + 1], a1);
            c0 = ffma2(whB[j], hk[j], c0);
            c1 = ffma2(whB[j + 1], hk[j + 1], c1);
        }
        ghAc = fold2(fadd2(a0, a1));
        ghBc = fold2(fadd2(c0, c1));
    }
    CBAR();

    // ================= decoder =================
    for (int t = 1; t < SS; t++) {
        // gi from x_{t-1}; gh carried
        u64 ai0 = pack2(biA, 0.f), ai1 = 0, bi0 = pack2(biB, 0.f), bi1 = 0;
#pragma unroll
        for (int j = 0; j < 18; j += 2) {
            u64 xk0 = *(const u64*)(xsh + 2 * j);
            u64 xk1 = *(const u64*)(xsh + 2 * j + 2);
            ai0 = ffma2(wiA[j], xk0, ai0);
            ai1 = ffma2(wiA[j + 1], xk1, ai1);
            bi0 = ffma2(wiB[j], xk0, bi0);
            bi1 = ffma2(wiB[j + 1], xk1, bi1);
        }
        float giA = fold2(fadd2(ai0, ai1));
        float giB = fold2(fadd2(bi0, bi1));
        float ghA = ghAc, ghB = ghBc;
        float s_iA = __shfl_sync(FULLM, giA, nsrc);
        float s_iB = __shfl_sync(FULLM, giB, nsrc);
        float s_hA = __shfl_sync(FULLM, ghA, nsrc);
        float s_hB = __shfl_sync(FULLM, ghB, nsrc);
        float in = nlo ? s_iA : s_iB;
        float hn = nlo ? s_hA : s_hB;
        float r = siga(giA + ghA);
        float z = siga(giB + ghB);
        float n = tanha(fmaf(r, hn, in));
        hreg = tanha(fmaf(z, hreg - n, n));
        hsh[lane] = hreg;
        CBAR();
        // load hk once: FC (this step) + gh (next step)
        u64 hk[10];
#pragma unroll
        for (int j = 0; j < 10; j++) hk[j] = *(const u64*)(hsh + 2 * j);
        u64 f0a = pack2(bf0, 0.f), f0b = 0, f1a = pack2(bf1, 0.f), f1b = 0;
#pragma unroll
        for (int j = 0; j < 10; j += 2) {
            f0a = ffma2(wf0[j], hk[j], f0a);
            f0b = ffma2(wf0[j + 1], hk[j + 1], f0b);
            f1a = ffma2(wf1[j], hk[j], f1a);
            f1b = ffma2(wf1[j + 1], hk[j + 1], f1b);
        }
        float v0 = tanha(fold2(fadd2(f0a, f0b)));
        float v1 = tanha(fold2(fadd2(f1a, f1b)));
        *(float2*)(xsh + 2 * lane) = make_float2(v0, v1);
        stg2_pred(predX, xsout + (size_t)(SS - 1 - t) * FF + 2 * lane, v0, v1);
        u64 a0 = pack2(bhA, 0.f), a1 = 0, c0 = pack2(bhB, 0.f), c1 = 0;
#pragma unroll
        for (int j = 0; j < 10; j += 2) {
            a0 = ffma2(whA[j], hk[j], a0);
            a1 = ffma2(whA[j + 1], hk[j + 1], a1);
            c0 = ffma2(whB[j], hk[j], c0);
            c1 = ffma2(whB[j + 1], hk[j + 1], c1);
        }
        ghAc = fold2(fadd2(a0, a1));
        ghBc = fold2(fadd2(c0, c1));
        CBAR();
    }
}

extern "C" void kernel_launch(void* const* d_in, const int* in_sizes, int n_in,
                              void* d_out, int out_size) {
    const float* x    = (const float*)d_in[0];
    const int*   oneh = (const int*)d_in[1];
    const float* e0   = (const float*)d_in[2];
    const float* e1   = (const float*)d_in[3];
    const float* e2   = (const float*)d_in[4];
    const float* e3   = (const float*)d_in[5];
    const float* Wih1 = (const float*)d_in[6];
    const float* Whh1 = (const float*)d_in[7];
    const float* bih1 = (const float*)d_in[8];
    const float* bhh1 = (const float*)d_in[9];
    const float* Wih2 = (const float*)d_in[10];
    const float* Whh2 = (const float*)d_in[11];
    const float* bih2 = (const float*)d_in[12];
    const float* bhh2 = (const float*)d_in[13];
    const float* Wfc  = (const float*)d_in[14];
    const float* bfc  = (const float*)d_in[15];
    float* out = (float*)d_out;

    k1_pregate<<<4096, 256>>>(x, oneh, e0, e1, e2, e3, Wih1, bih1, out);
    k2_recur<<<128, 256>>>(Whh1, bhh1, Wih2, Whh2, bih2, bhh2, Wfc, bfc, out);
}

// round 9
// speedup vs baseline: 2.0558x; 1.2393x over previous
#include <cuda_runtime.h>

// GruAeModel: B=1024, S=1024, F=36, H=20.
// Round 7: single fused kernel. Encoder computes gi=Wih1@x inline, pipelined
// 2 steps ahead (fills idle issue slots of the chain-bound recurrence).
// No scratch, no second kernel. Decoder identical to R6.

#define HH 20
#define FF 36
#define RR 12
#define BB 1024
#define SS 1024
#define FULLM 0xffffffffu

typedef unsigned long long u64;

#define CBAR() asm volatile("" ::: "memory")

__device__ __forceinline__ u64 ffma2(u64 a, u64 b, u64 c) {
    u64 d;
    asm("fma.rn.f32x2 %0, %1, %2, %3;" : "=l"(d) : "l"(a), "l"(b), "l"(c));
    return d;
}
__device__ __forceinline__ u64 fadd2(u64 a, u64 b) {
    u64 d;
    asm("add.rn.f32x2 %0, %1, %2;" : "=l"(d) : "l"(a), "l"(b));
    return d;
}
__device__ __forceinline__ float fold2(u64 a) {
    float lo = __uint_as_float((unsigned)a);
    float hi = __uint_as_float((unsigned)(a >> 32));
    return lo + hi;
}
__device__ __forceinline__ u64 pack2(float lo, float hi) {
    u64 d;
    asm("mov.b64 %0, {%1, %2};" : "=l"(d) : "f"(lo), "f"(hi));
    return d;
}
__device__ __forceinline__ float tanha(float x) {
    float y;
    asm("tanh.approx.f32 %0, %1;" : "=f"(y) : "f"(x));
    return y;
}
__device__ __forceinline__ float siga(float x) {
    return fmaf(0.5f, tanha(0.5f * x), 0.5f);
}
__device__ __forceinline__ int imin(int a, int b) { return a < b ? a : b; }

__device__ __forceinline__ void stg_pred(int p, float* addr, float v) {
    asm volatile("{.reg .pred q; setp.ne.s32 q, %0, 0; @q st.global.f32 [%1], %2;}"
                 :: "r"(p), "l"(addr), "f"(v));
}
__device__ __forceinline__ void stg2_pred(int p, float* addr, float v0, float v1) {
    asm volatile("{.reg .pred q; setp.ne.s32 q, %0, 0; @q st.global.v2.f32 [%1], {%2,%3};}"
                 :: "r"(p), "l"(addr), "f"(v0), "f"(v1));
}

// gate mapping: lane<20: gA=row lane (r), gB=row 20+lane (z)
// lane 20+k (k<10): gA=row 40+k (n lo), gB=row 50+k (n hi); lanes 30,31 junk.

__global__ __launch_bounds__(256, 1) void gruae_fused(
    const float* __restrict__ x, const int* __restrict__ oneh,
    const float* __restrict__ e0t, const float* __restrict__ e1t,
    const float* __restrict__ e2t, const float* __restrict__ e3t,
    const float* __restrict__ Wih1, const float* __restrict__ Whh1,
    const float* __restrict__ bih1, const float* __restrict__ bhh1,
    const float* __restrict__ Wih2, const float* __restrict__ Whh2,
    const float* __restrict__ bih2, const float* __restrict__ bhh2,
    const float* __restrict__ Wfc, const float* __restrict__ bfc,
    float* __restrict__ out) {
    __shared__ __align__(16) float etab[1320];   // e0(40) e1@40 e2@120 e3@520
    __shared__ __align__(16) float XS[8][64];    // x build/exchange (pad, junk hi)
    __shared__ __align__(16) float HS[8][32];    // h (junk 20..31)

    const int tid = threadIdx.x;
    const int wid = tid >> 5;
    const int lane = tid & 31;

    for (int i = tid; i < 40; i += 256) etab[i] = e0t[i];
    for (int i = tid; i < 80; i += 256) etab[40 + i] = e1t[i];
    for (int i = tid; i < 400; i += 256) etab[120 + i] = e2t[i];
    for (int i = tid; i < 800; i += 256) etab[520 + i] = e3t[i];

    const int b = blockIdx.x * 8 + wid;
    float* const xsh = XS[wid];
    float* const hsh = HS[wid];

    const int gA = (lane < 20) ? lane : lane + 20;
    const int gB = imin((lane < 20) ? lane + 20 : lane + 30, 59);
    const int nsrc = 20 + (lane % 10);
    const bool nlo = (lane < 10);

    // encoder weights: Wih1 rows gA,gB + Whh1 rows gA,gB
    u64 wiA[18], wiB[18], whA[10], whB[10];
    {
        const u64* ra = (const u64*)(Wih1 + gA * FF);
        const u64* rb = (const u64*)(Wih1 + gB * FF);
#pragma unroll
        for (int j = 0; j < 18; j++) { wiA[j] = ra[j]; wiB[j] = rb[j]; }
        const u64* ha = (const u64*)(Whh1 + gA * HH);
        const u64* hb = (const u64*)(Whh1 + gB * HH);
#pragma unroll
        for (int j = 0; j < 10; j++) { whA[j] = ha[j]; whB[j] = hb[j]; }
    }
    float biA = bih1[gA], biB = bih1[gB];
    float bhA = bhh1[gA], bhB = bhh1[gB];
    hsh[lane] = 0.f;

    // feature-map constants (branch-free xin build)
    const int osrc = (lane < 16) ? 12 : (lane < 20) ? 13 : (lane < 28) ? 14 : 15;
    const int tscale = (lane < 20) ? 4 : 8;
    const int tadd = ((lane < 16) ? (0 - 12) : (lane < 20) ? (40 - 16)
                      : (lane < 28) ? (120 - 20) : (520 - 28)) + lane;

    // unified input stream: lanes<12 raw x cols, 12..15 onehot cols, 16+ dup 15
    const int lc = imin(lane, 15);
    const unsigned* const up = (lc < 12)
        ? (const unsigned*)(x + (size_t)b * SS * RR + lc)
        : (const unsigned*)(oneh + (size_t)b * SS * 4 + (lc - 12));
    const int stride = (lc < 12) ? RR : 4;
    unsigned q0 = up[0], q1 = up[stride], q2 = up[2 * stride];

    float* const origin = out + (size_t)b * SS * FF;
    __syncthreads();

    // build xin(u) in smem, write origin(u), compute gi(u) = Wih1@xin + bih1
    auto build_gi = [&](int u, float& giA_o, float& giB_o) {
        int o = __shfl_sync(FULLM, (int)q0, osrc);
        int o3 = __shfl_sync(FULLM, (int)q0, 15);
        float ev = etab[tadd + o * tscale];
        float v = (lane < 12) ? __uint_as_float(q0) : ev;
        float v2 = etab[520 + o3 * 8 + 4 + (lane & 3)];
        q0 = q1; q1 = q2;
        q2 = up[(size_t)imin(u + 3, SS - 1) * stride];
        xsh[lane] = v;
        xsh[32 + lane] = v2;
        const int inb = (u < SS);
        stg_pred(inb, origin + (size_t)u * FF + lane, v);
        stg_pred(inb && (lane < 4), origin + (size_t)u * FF + 32 + lane, v2);
        CBAR();
        u64 a0 = pack2(biA, 0.f), a1 = 0, c0 = pack2(biB, 0.f), c1 = 0;
#pragma unroll
        for (int j = 0; j < 18; j += 2) {
            u64 xk0 = *(const u64*)(xsh + 2 * j);
            u64 xk1 = *(const u64*)(xsh + 2 * j + 2);
            a0 = ffma2(wiA[j], xk0, a0);
            a1 = ffma2(wiA[j + 1], xk1, a1);
            c0 = ffma2(wiB[j], xk0, c0);
            c1 = ffma2(wiB[j + 1], xk1, c1);
        }
        giA_o = fold2(fadd2(a0, a1));
        giB_o = fold2(fadd2(c0, c1));
        CBAR();
    };

    float giA0, giB0, giA1, giB1;
    build_gi(0, giA0, giB0);
    build_gi(1, giA1, giB1);

    float hreg = 0.f;
    // ================= encoder (fused gi pipeline, +2 ahead) =================
    for (int t = 0; t < SS; t++) {
        float giA2, giB2;
        build_gi(t + 2, giA2, giB2);
        u64 a0 = pack2(bhA, 0.f), a1 = 0, c0 = pack2(bhB, 0.f), c1 = 0;
#pragma unroll
        for (int j = 0; j < 10; j += 2) {
            u64 hk0 = *(const u64*)(hsh + 2 * j);
            u64 hk1 = *(const u64*)(hsh + 2 * j + 2);
            a0 = ffma2(whA[j], hk0, a0);
            a1 = ffma2(whA[j + 1], hk1, a1);
            c0 = ffma2(whB[j], hk0, c0);
            c1 = ffma2(whB[j + 1], hk1, c1);
        }
        float ghA = fold2(fadd2(a0, a1));
        float ghB = fold2(fadd2(c0, c1));
        float s_iA = __shfl_sync(FULLM, giA0, nsrc);
        float s_iB = __shfl_sync(FULLM, giB0, nsrc);
        float s_hA = __shfl_sync(FULLM, ghA, nsrc);
        float s_hB = __shfl_sync(FULLM, ghB, nsrc);
        float in = nlo ? s_iA : s_iB;
        float hn = nlo ? s_hA : s_hB;
        float r = siga(giA0 + ghA);
        float z = siga(giB0 + ghB);
        float n = tanha(fmaf(r, hn, in));
        hreg = fmaf(z, hreg - n, n);
        hsh[lane] = hreg;
        CBAR();
        giA0 = giA1; giB0 = giB1; giA1 = giA2; giB1 = giB2;
    }

    // ---- handoff + decoder weights ----
    hreg = tanha(hreg);
    hsh[lane] = hreg;
    {
        const u64* ra = (const u64*)(Wih2 + gA * FF);
        const u64* rb = (const u64*)(Wih2 + gB * FF);
#pragma unroll
        for (int j = 0; j < 18; j++) { wiA[j] = ra[j]; wiB[j] = rb[j]; }
        const u64* ha = (const u64*)(Whh2 + gA * HH);
        const u64* hb = (const u64*)(Whh2 + gB * HH);
#pragma unroll
        for (int j = 0; j < 10; j++) { whA[j] = ha[j]; whB[j] = hb[j]; }
    }
    biA = bih2[gA]; biB = bih2[gB];
    bhA = bhh2[gA]; bhB = bhh2[gB];
    u64 wf0[10], wf1[10];
    const int fr0 = (lane < 18) ? 2 * lane : 0;
    const int fr1 = (lane < 18) ? 2 * lane + 1 : 0;
    {
        const u64* f0 = (const u64*)(Wfc + fr0 * HH);
        const u64* f1 = (const u64*)(Wfc + fr1 * HH);
#pragma unroll
        for (int j = 0; j < 10; j++) { wf0[j] = f0[j]; wf1[j] = f1[j]; }
    }
    const float bf0 = bfc[fr0], bf1 = bfc[fr1];
    float* const xsout = out + (size_t)(BB + b) * SS * FF;
    const int predX = (lane < 18);
    CBAR();

    // t=0: load hk once; FC -> x0; gh matvec carried into loop
    float ghAc, ghBc;
    {
        u64 hk[10];
#pragma unroll
        for (int j = 0; j < 10; j++) hk[j] = *(const u64*)(hsh + 2 * j);
        u64 f0a = pack2(bf0, 0.f), f0b = 0, f1a = pack2(bf1, 0.f), f1b = 0;
#pragma unroll
        for (int j = 0; j < 10; j += 2) {
            f0a = ffma2(wf0[j], hk[j], f0a);
            f0b = ffma2(wf0[j + 1], hk[j + 1], f0b);
            f1a = ffma2(wf1[j], hk[j], f1a);
            f1b = ffma2(wf1[j + 1], hk[j + 1], f1b);
        }
        float v0 = tanha(fold2(fadd2(f0a, f0b)));
        float v1 = tanha(fold2(fadd2(f1a, f1b)));
        *(float2*)(xsh + 2 * lane) = make_float2(v0, v1);
        stg2_pred(predX, xsout + (size_t)(SS - 1) * FF + 2 * lane, v0, v1);
        u64 a0 = pack2(bhA, 0.f), a1 = 0, c0 = pack2(bhB, 0.f), c1 = 0;
#pragma unroll
        for (int j = 0; j < 10; j += 2) {
            a0 = ffma2(whA[j], hk[j], a0);
            a1 = ffma2(whA[j + 1], hk[j + 1], a1);
            c0 = ffma2(whB[j], hk[j], c0);
            c1 = ffma2(whB[j + 1], hk[j + 1], c1);
        }
        ghAc = fold2(fadd2(a0, a1));
        ghBc = fold2(fadd2(c0, c1));
    }
    CBAR();

    // ================= decoder =================
    for (int t = 1; t < SS; t++) {
        u64 ai0 = pack2(biA, 0.f), ai1 = 0, bi0 = pack2(biB, 0.f), bi1 = 0;
#pragma unroll
        for (int j = 0; j < 18; j += 2) {
            u64 xk0 = *(const u64*)(xsh + 2 * j);
            u64 xk1 = *(const u64*)(xsh + 2 * j + 2);
            ai0 = ffma2(wiA[j], xk0, ai0);
            ai1 = ffma2(wiA[j + 1], xk1, ai1);
            bi0 = ffma2(wiB[j], xk0, bi0);
            bi1 = ffma2(wiB[j + 1], xk1, bi1);
        }
        float giA = fold2(fadd2(ai0, ai1));
        float giB = fold2(fadd2(bi0, bi1));
        float s_iA = __shfl_sync(FULLM, giA, nsrc);
        float s_iB = __shfl_sync(FULLM, giB, nsrc);
        float s_hA = __shfl_sync(FULLM, ghAc, nsrc);
        float s_hB = __shfl_sync(FULLM, ghBc, nsrc);
        float in = nlo ? s_iA : s_iB;
        float hn = nlo ? s_hA : s_hB;
        float r = siga(giA + ghAc);
        float z = siga(giB + ghBc);
        float n = tanha(fmaf(r, hn, in));
        hreg = tanha(fmaf(z, hreg - n, n));
        hsh[lane] = hreg;
        CBAR();
        // load hk once: FC (this step) + gh (next step)
        u64 hk[10];
#pragma unroll
        for (int j = 0; j < 10; j++) hk[j] = *(const u64*)(hsh + 2 * j);
        u64 f0a = pack2(bf0, 0.f), f0b = 0, f1a = pack2(bf1, 0.f), f1b = 0;
#pragma unroll
        for (int j = 0; j < 10; j += 2) {
            f0a = ffma2(wf0[j], hk[j], f0a);
            f0b = ffma2(wf0[j + 1], hk[j + 1], f0b);
            f1a = ffma2(wf1[j], hk[j], f1a);
            f1b = ffma2(wf1[j + 1], hk[j + 1], f1b);
        }
        float v0 = tanha(fold2(fadd2(f0a, f0b)));
        float v1 = tanha(fold2(fadd2(f1a, f1b)));
        *(float2*)(xsh + 2 * lane) = make_float2(v0, v1);
        stg2_pred(predX, xsout + (size_t)(SS - 1 - t) * FF + 2 * lane, v0, v1);
        u64 a0 = pack2(bhA, 0.f), a1 = 0, c0 = pack2(bhB, 0.f), c1 = 0;
#pragma unroll
        for (int j = 0; j < 10; j += 2) {
            a0 = ffma2(whA[j], hk[j], a0);
            a1 = ffma2(whA[j + 1], hk[j + 1], a1);
            c0 = ffma2(whB[j], hk[j], c0);
            c1 = ffma2(whB[j + 1], hk[j + 1], c1);
        }
        ghAc = fold2(fadd2(a0, a1));
        ghBc = fold2(fadd2(c0, c1));
        CBAR();
    }
}

extern "C" void kernel_launch(void* const* d_in, const int* in_sizes, int n_in,
                              void* d_out, int out_size) {
    const float* x    = (const float*)d_in[0];
    const int*   oneh = (const int*)d_in[1];
    const float* e0   = (const float*)d_in[2];
    const float* e1   = (const float*)d_in[3];
    const float* e2   = (const float*)d_in[4];
    const float* e3   = (const float*)d_in[5];
    const float* Wih1 = (const float*)d_in[6];
    const float* Whh1 = (const float*)d_in[7];
    const float* bih1 = (const float*)d_in[8];
    const float* bhh1 = (const float*)d_in[9];
    const float* Wih2 = (const float*)d_in[10];
    const float* Whh2 = (const float*)d_in[11];
    const float* bih2 = (const float*)d_in[12];
    const float* bhh2 = (const float*)d_in[13];
    const float* Wfc  = (const float*)d_in[14];
    const float* bfc  = (const float*)d_in[15];

    gruae_fused<<<BB / 8, 256>>>(
        x, oneh, e0, e1, e2, e3, Wih1, Whh1, bih1, bhh1,
        Wih2, Whh2, bih2, bhh2, Wfc, bfc, (float*)d_out);
}